// round 10
// baseline (speedup 1.0000x reference)
#include <cuda_runtime.h>
#include <cuda_bf16.h>

#define NUM_P 41          // pred labels 0..40
#define NUM_C 26          // gt labels 0..25
#define BINS  (NUM_P * NUM_C)   // 1066
#define PAIRS (BINS / 2)        // 533
#define HIST_BLOCKS 1184        // 148 SMs * 8
#define HIST_THREADS 256

// Global scratch: bin pairs packed into 64-bit words (lo = bin 2k, hi = bin 2k+1).
// Zero at module load; finalize re-zeroes after use so graph replays start clean.
// Per-bin totals <= 2^24, so 64-bit adds never carry across the 32-bit boundary.
__device__ unsigned long long g_counts64[PAIRS];

__global__ void __launch_bounds__(HIST_THREADS)
hist_kernel(const float4* __restrict__ pred4, const int4* __restrict__ gt4,
            const float* __restrict__ pred, const int* __restrict__ gt,
            int n4, int n) {
    __shared__ unsigned int h[BINS];
    for (int i = threadIdx.x; i < BINS; i += HIST_THREADS) h[i] = 0u;
    __syncthreads();

    const int stride = gridDim.x * HIST_THREADS;
    int i = blockIdx.x * HIST_THREADS + threadIdx.x;

    // Main loop: 2 float4 + 2 int4 loads in flight per iteration (MLP ~4)
    for (; i + stride < n4; i += 2 * stride) {
        float4 p0 = pred4[i];
        int4   g0 = gt4[i];
        float4 p1 = pred4[i + stride];
        int4   g1 = gt4[i + stride];
        atomicAdd(&h[__float2int_rn(p0.x) * NUM_C + g0.x], 1u);
        atomicAdd(&h[__float2int_rn(p0.y) * NUM_C + g0.y], 1u);
        atomicAdd(&h[__float2int_rn(p0.z) * NUM_C + g0.z], 1u);
        atomicAdd(&h[__float2int_rn(p0.w) * NUM_C + g0.w], 1u);
        atomicAdd(&h[__float2int_rn(p1.x) * NUM_C + g1.x], 1u);
        atomicAdd(&h[__float2int_rn(p1.y) * NUM_C + g1.y], 1u);
        atomicAdd(&h[__float2int_rn(p1.z) * NUM_C + g1.z], 1u);
        atomicAdd(&h[__float2int_rn(p1.w) * NUM_C + g1.w], 1u);
    }
    for (; i < n4; i += stride) {
        float4 p = pred4[i];
        int4   g = gt4[i];
        atomicAdd(&h[__float2int_rn(p.x) * NUM_C + g.x], 1u);
        atomicAdd(&h[__float2int_rn(p.y) * NUM_C + g.y], 1u);
        atomicAdd(&h[__float2int_rn(p.z) * NUM_C + g.z], 1u);
        atomicAdd(&h[__float2int_rn(p.w) * NUM_C + g.w], 1u);
    }
    int tail_start = n4 * 4;
    for (int j = tail_start + blockIdx.x * HIST_THREADS + threadIdx.x; j < n;
         j += stride) {
        atomicAdd(&h[__float2int_rn(pred[j]) * NUM_C + gt[j]], 1u);
    }

    __syncthreads();
    // Flush: pack two 32-bit bins into one 64-bit global atomic (halves ATOMG count)
    for (int k = threadIdx.x; k < PAIRS; k += HIST_THREADS) {
        unsigned int lo = h[2 * k];
        unsigned int hi = h[2 * k + 1];
        if (lo | hi)
            atomicAdd(&g_counts64[k],
                      (unsigned long long)lo | ((unsigned long long)hi << 32));
    }
}

// Single block, 256 threads: flat parallel sweep of the 1066 bins into smem
// integer accumulators (exact), then the 41x26 reduction, then scratch reset.
__global__ void __launch_bounds__(256)
finalize_kernel(float* __restrict__ out) {
    __shared__ unsigned int s_ps[NUM_P];     // pred sizes (integer, exact)
    __shared__ unsigned int s_gs[NUM_C];     // gt sizes
    __shared__ unsigned int s_om[NUM_P];     // overlap bits (c>=1)
    __shared__ unsigned int s_present;
    __shared__ float        s_dice[64];
    __shared__ float        s_fp[64];

    const int t = threadIdx.x;
    const unsigned int* gc = (const unsigned int*)g_counts64;  // bin k at gc[k]

    if (t < NUM_P) { s_ps[t] = 0u; s_om[t] = 0u; }
    if (t < NUM_C) s_gs[t] = 0u;
    __syncthreads();

    for (int k = t; k < BINS; k += 256) {
        unsigned int v = gc[k];
        int p = k / NUM_C;
        int c = k - p * NUM_C;
        if (v) {
            atomicAdd(&s_ps[p], v);
            atomicAdd(&s_gs[c], v);
            if (c >= 1) atomicOr(&s_om[p], 1u << c);
        }
    }
    __syncthreads();

    if (t == 0) {
        unsigned int pm = 0u;
        for (int c = 1; c < NUM_C; c++)
            if (s_gs[c] > 0u) pm |= (1u << c);
        s_present = pm;
    }
    __syncthreads();
    const unsigned int pm = s_present;

    if (t < 64) {
        float contrib = 0.0f;
        if (t >= 1 && t < NUM_C && ((pm >> t) & 1u)) {
            float us = 0.0f;
            #pragma unroll
            for (int p = 0; p < NUM_P; p++)
                if ((s_om[p] >> t) & 1u) us += (float)s_ps[p];
            float gs = (float)s_gs[t];
            contrib = 2.0f * gs / (us + gs + 1.0f);
        }
        float fpc = 0.0f;
        if (t < NUM_P && s_ps[t] > 0u && (s_om[t] & pm) == 0u)
            fpc = 1.0f;
        s_dice[t] = contrib;
        s_fp[t]   = fpc;
    }
    __syncthreads();

    if (t == 0) {
        float lesion_dice = 0.0f, fp = 0.0f;
        for (int k = 0; k < 64; k++) { lesion_dice += s_dice[k]; fp += s_fp[k]; }
        float num_gt = (float)__popc(pm);
        out[0] = lesion_dice / (num_gt + fp);
    }
    __syncthreads();

    // Reset scratch for the next graph replay (deterministic across runs).
    for (int k = t; k < PAIRS; k += 256) g_counts64[k] = 0ull;
}

extern "C" void kernel_launch(void* const* d_in, const int* in_sizes, int n_in,
                              void* d_out, int out_size) {
    const float* pred = (const float*)d_in[0];
    const int*   gt   = (const int*)d_in[1];
    float* out = (float*)d_out;
    const int n  = in_sizes[0];
    const int n4 = n >> 2;

    hist_kernel<<<HIST_BLOCKS, HIST_THREADS>>>(
        (const float4*)pred, (const int4*)gt, pred, gt, n4, n);
    finalize_kernel<<<1, 256>>>(out);
}